// round 14
// baseline (speedup 1.0000x reference)
#include <cuda_runtime.h>
#include <cuda_fp16.h>
#include <math.h>
#include <cstdint>

// Problem dims
#define B_   2
#define S_   2048
#define H_   2048
#define NH_  32
#define NKV_ 8
#define HD_  64

// fp32 scratch (pre-rope Q/K/V)
__device__ float g_q[(size_t)B_ * S_ * NH_ * HD_];
__device__ float g_k[(size_t)B_ * S_ * NKV_ * HD_];
__device__ float g_v[(size_t)B_ * S_ * NKV_ * HD_];

// RoPE tables
__device__ float g_cos[S_ * 32];
__device__ float g_sin[S_ * 32];

// fp16 scratch
__device__ __half g_hs_hi[(size_t)B_ * S_ * H_];
__device__ __half g_hs_lo[(size_t)B_ * S_ * H_];
__device__ __half g_wq_hi[(size_t)H_ * H_];
__device__ __half g_wk_hi[(size_t)NKV_ * HD_ * H_];
__device__ __half g_wv_hi[(size_t)NKV_ * HD_ * H_];
__device__ __half g_wo_hi[(size_t)H_ * H_];
__device__ __half g_oh_hi[(size_t)B_ * S_ * NH_ * HD_];
__device__ __half g_oh_lo[(size_t)B_ * S_ * NH_ * HD_];
// attention operands, head-major [B, heads, S, HD]
__device__ __half g_qh[(size_t)B_ * NH_ * S_ * HD_];
__device__ __half g_ql[(size_t)B_ * NH_ * S_ * HD_];
__device__ __half g_kh2[(size_t)B_ * NKV_ * S_ * HD_];
__device__ __half g_vh2[(size_t)B_ * NKV_ * S_ * HD_];

// ---- mma.sync / ldmatrix / cp.async helpers ----
__device__ __forceinline__ uint32_t smem_u32(const void* p) {
    uint32_t a;
    asm("{ .reg .u64 t; cvta.to.shared.u64 t, %1; cvt.u32.u64 %0, t; }" : "=r"(a) : "l"(p));
    return a;
}
__device__ __forceinline__ void ldmx4(uint32_t* r, uint32_t addr) {
    asm volatile("ldmatrix.sync.aligned.m8n8.x4.shared.b16 {%0,%1,%2,%3}, [%4];"
                 : "=r"(r[0]), "=r"(r[1]), "=r"(r[2]), "=r"(r[3]) : "r"(addr));
}
__device__ __forceinline__ void ldmx4t(uint32_t* r, uint32_t addr) {
    asm volatile("ldmatrix.sync.aligned.m8n8.x4.trans.shared.b16 {%0,%1,%2,%3}, [%4];"
                 : "=r"(r[0]), "=r"(r[1]), "=r"(r[2]), "=r"(r[3]) : "r"(addr));
}
__device__ __forceinline__ void mma16816(float* c, const uint32_t* a, uint32_t b0, uint32_t b1) {
    asm volatile("mma.sync.aligned.m16n8k16.row.col.f32.f16.f16.f32 "
                 "{%0,%1,%2,%3}, {%4,%5,%6,%7}, {%8,%9}, {%0,%1,%2,%3};"
                 : "+f"(c[0]), "+f"(c[1]), "+f"(c[2]), "+f"(c[3])
                 : "r"(a[0]), "r"(a[1]), "r"(a[2]), "r"(a[3]), "r"(b0), "r"(b1));
}
__device__ __forceinline__ void cp16(uint32_t s, const void* g) {
    asm volatile("cp.async.ca.shared.global [%0], [%1], 16;" :: "r"(s), "l"(g));
}
#define CP_COMMIT() asm volatile("cp.async.commit_group;" ::: "memory")
#define CP_WAIT0()  asm volatile("cp.async.wait_group 0;" ::: "memory")

__device__ __forceinline__ uint32_t pkhf(float x, float y) {
    __half2 t = __floats2half2_rn(x, y);
    return *(uint32_t*)&t;
}
__device__ __forceinline__ void splitpk(float x, float y, uint32_t& hi, uint32_t& lo) {
    float hx = __half2float(__float2half_rn(x));
    float hy = __half2float(__float2half_rn(y));
    hi = pkhf(hx, hy);
    lo = pkhf(x - hx, y - hy);
}

// ============================================================================
// sincos table init: g_cos/g_sin[s*32+d] (identical math to prior sincosf use)
// ============================================================================
__global__ void sincos_init_kernel()
{
    int idx = blockIdx.x * blockDim.x + threadIdx.x;
    if (idx >= S_ * 32) return;
    int d = idx & 31, s = idx >> 5;
    float inv = exp2f((float)d * -0.41524101186f);
    float fr = (float)s * inv;
    float c, sn;
    sincosf(fr, &sn, &c);
    g_cos[idx] = c;
    g_sin[idx] = sn;
}

// ============================================================================
// split: fp32 -> fp16 hi + lo
// ============================================================================
__global__ void split_kernel(const float* __restrict__ x,
                             __half* __restrict__ hi,
                             __half* __restrict__ lo, int n4)
{
    int i = blockIdx.x * blockDim.x + threadIdx.x;
    if (i >= n4) return;
    float4 v = *(const float4*)(x + (size_t)i * 4);
    float h0 = __half2float(__float2half_rn(v.x));
    float h1 = __half2float(__float2half_rn(v.y));
    float h2 = __half2float(__float2half_rn(v.z));
    float h3 = __half2float(__float2half_rn(v.w));
    *(uint32_t*)(hi + (size_t)i * 4)     = pkhf(h0, h1);
    *(uint32_t*)(hi + (size_t)i * 4 + 2) = pkhf(h2, h3);
    *(uint32_t*)(lo + (size_t)i * 4)     = pkhf(v.x - h0, v.y - h1);
    *(uint32_t*)(lo + (size_t)i * 4 + 2) = pkhf(v.z - h2, v.w - h3);
}

// round all four weight matrices in one launch
#define N4_WQ 1048576
#define N4_WK 262144
#define N4_WV 262144
#define N4_WO 1048576
__global__ void round4_kernel(const float* __restrict__ wq, const float* __restrict__ wk,
                              const float* __restrict__ wv, const float* __restrict__ wo,
                              __half* __restrict__ oq, __half* __restrict__ ok,
                              __half* __restrict__ ov, __half* __restrict__ oo)
{
    int i = blockIdx.x * blockDim.x + threadIdx.x;
    const float* src; __half* dst; int j;
    if (i < N4_WQ)                      { src = wq; dst = oq; j = i; }
    else if (i < N4_WQ + N4_WK)         { src = wk; dst = ok; j = i - N4_WQ; }
    else if (i < N4_WQ + N4_WK + N4_WV) { src = wv; dst = ov; j = i - N4_WQ - N4_WK; }
    else if (i < N4_WQ + N4_WK + N4_WV + N4_WO)
                                        { src = wo; dst = oo; j = i - N4_WQ - N4_WK - N4_WV; }
    else return;
    float4 v = *(const float4*)(src + (size_t)j * 4);
    *(uint32_t*)(dst + (size_t)j * 4)     = pkhf(v.x, v.y);
    *(uint32_t*)(dst + (size_t)j * 4 + 2) = pkhf(v.z, v.w);
}

// ============================================================================
// Fused prep: rope+split(Q) | rope+round(K, scale 1/8) | round(V) -> head-major
// ============================================================================
#define PREP_NQ (B_ * S_ * NH_ * 32)            // 4194304
#define PREP_NK (B_ * S_ * NKV_ * 32)           // 1048576
#define PREP_NV (B_ * S_ * NKV_ * HD_ / 4)      // 1048576
__global__ void prep_kernel(const float* __restrict__ q, const float* __restrict__ k,
                            const float* __restrict__ v,
                            __half* __restrict__ qh, __half* __restrict__ ql,
                            __half* __restrict__ kh, __half* __restrict__ vh)
{
    int idx = blockIdx.x * blockDim.x + threadIdx.x;
    if (idx < PREP_NQ) {
        int d = idx & 31;
        int r = idx >> 5;
        int h = r & 31; r >>= 5;
        int s = r & (S_ - 1);
        int b = r >> 11;
        float c = g_cos[(s << 5) + d], sn = g_sin[(s << 5) + d];
        size_t src = (((size_t)b * S_ + s) * NH_ + h) * HD_;
        float x0 = q[src + d], x1 = q[src + d + 32];
        float y0 = x0 * c - x1 * sn;
        float y1 = x1 * c + x0 * sn;
        size_t dst = (((size_t)b * NH_ + h) * S_ + s) * HD_;
        float h0 = __half2float(__float2half_rn(y0));
        float h1 = __half2float(__float2half_rn(y1));
        qh[dst + d]      = __float2half_rn(h0);
        qh[dst + d + 32] = __float2half_rn(h1);
        ql[dst + d]      = __float2half_rn(y0 - h0);
        ql[dst + d + 32] = __float2half_rn(y1 - h1);
        return;
    }
    int i2 = idx - PREP_NQ;
    if (i2 < PREP_NK) {
        int d = i2 & 31;
        int r = i2 >> 5;
        int h = r & 7; r >>= 3;
        int s = r & (S_ - 1);
        int b = r >> 11;
        float c = g_cos[(s << 5) + d], sn = g_sin[(s << 5) + d];
        size_t src = (((size_t)b * S_ + s) * NKV_ + h) * HD_;
        float x0 = k[src + d], x1 = k[src + d + 32];
        size_t dst = (((size_t)b * NKV_ + h) * S_ + s) * HD_;
        kh[dst + d]      = __float2half_rn((x0 * c - x1 * sn) * 0.125f);
        kh[dst + d + 32] = __float2half_rn((x1 * c + x0 * sn) * 0.125f);
        return;
    }
    int i3 = i2 - PREP_NK;
    if (i3 >= PREP_NV) return;
    int d4 = i3 & 15; int r = i3 >> 4;
    int h = r & 7; r >>= 3;
    int s = r & (S_ - 1);
    int b = r >> 11;
    float4 vv = *(const float4*)(v + ((((size_t)b * S_ + s) * NKV_ + h) * HD_) + d4 * 4);
    size_t dst = (((size_t)b * NKV_ + h) * S_ + s) * HD_ + d4 * 4;
    *(uint32_t*)(vh + dst)     = pkhf(vv.x, vv.y);
    *(uint32_t*)(vh + dst + 2) = pkhf(vv.z, vv.w);
}

// ============================================================================
// HMMA GEMM body: C tile (bm,bn) = A[M,K] * W[N,K]^T, 2-term fp16, BK=64.
// 128x128 tile, 8 warps (2x4, 64x32 warp tiles), cp.async double buffer.
// Rows 128B + 16B pad (LDR 144) -> conflict-free ldmatrix.
// ============================================================================
#define GLDR  144
#define GTILE (128 * GLDR)      // 18432 B per operand tile
#define GSTG  (3 * GTILE)       // Ah, Al, Bh = 55296
#define GEMM_SMEM (2 * GSTG)    // 110592

#define PREFETCH(buf, kcv) do { \
    size_t goff = (size_t)(kcv) * 64 + lc32; \
    uint32_t sro = (buf) * GSTG + lrow * GLDR + lb64; \
    const char* _ga = (const char*)(Ahi + (size_t)(bm + lrow) * K + goff); \
    const char* _gl = (const char*)(Alo + (size_t)(bm + lrow) * K + goff); \
    const char* _gb = (const char*)(Bh  + (size_t)(bn + lrow) * K + goff); \
    cp16(sbase + sro,      _ga);      cp16(sbase + sro + 16, _ga + 16); \
    cp16(sbase + sro + 32, _ga + 32); cp16(sbase + sro + 48, _ga + 48); \
    cp16(sbase + sro + GTILE,      _gl);      cp16(sbase + sro + GTILE + 16, _gl + 16); \
    cp16(sbase + sro + GTILE + 32, _gl + 32); cp16(sbase + sro + GTILE + 48, _gl + 48); \
    cp16(sbase + sro + 2 * GTILE,      _gb);      cp16(sbase + sro + 2 * GTILE + 16, _gb + 16); \
    cp16(sbase + sro + 2 * GTILE + 32, _gb + 32); cp16(sbase + sro + 2 * GTILE + 48, _gb + 48); \
    CP_COMMIT(); \
} while (0)

__device__ __forceinline__ void gemm_body(
    const __half* __restrict__ Ahi, const __half* __restrict__ Alo,
    const __half* __restrict__ Bh, float* __restrict__ C,
    int N, int K, int bm, int bn, uint32_t sbase)
{
    const int tid = threadIdx.x;
    const int lane = tid & 31, w = tid >> 5;
    const int wm = (w >> 2) * 64, wn = (w & 3) * 32;
    const int lrow = tid >> 1;
    const int lc32 = (tid & 1) * 32;   // element offset (fp16)
    const int lb64 = (tid & 1) * 64;   // byte offset
    const int lmr = lane & 15, lmc = lane >> 4;

    float acc[4][4][4];
#pragma unroll
    for (int a = 0; a < 4; a++)
#pragma unroll
        for (int b = 0; b < 4; b++)
#pragma unroll
            for (int c = 0; c < 4; c++) acc[a][b][c] = 0.f;

    const int nch = K >> 6;
    PREFETCH(0, 0);

    for (int it = 0; it < nch; it++) {
        CP_WAIT0();
        __syncthreads();
        if (it + 1 < nch) PREFETCH((it + 1) & 1, it + 1);

        const uint32_t sAh = sbase + (it & 1) * GSTG;
        const uint32_t sAl = sAh + GTILE;
        const uint32_t sBh = sAh + 2 * GTILE;
#pragma unroll
        for (int kk = 0; kk < 4; kk++) {
            uint32_t bh[2][4];
#pragma unroll
            for (int nh = 0; nh < 2; nh++)
                ldmx4(bh[nh], sBh + (wn + nh * 16 + lmr) * GLDR + (kk * 2 + lmc) * 16);
#pragma unroll
            for (int mi = 0; mi < 4; mi++) {
                uint32_t ah[4], al[4];
                uint32_t ro = (wm + mi * 16 + lmr) * GLDR + (kk * 2 + lmc) * 16;
                ldmx4(ah, sAh + ro);
                ldmx4(al, sAl + ro);
#pragma unroll
                for (int nh = 0; nh < 2; nh++) {
                    mma16816(acc[mi][nh * 2 + 0], ah, bh[nh][0], bh[nh][2]);
                    mma16816(acc[mi][nh * 2 + 1], ah, bh[nh][1], bh[nh][3]);
                    mma16816(acc[mi][nh * 2 + 0], al, bh[nh][0], bh[nh][2]);
                    mma16816(acc[mi][nh * 2 + 1], al, bh[nh][1], bh[nh][3]);
                }
            }
        }
        __syncthreads();
    }

    const int er = lane >> 2, ec = (lane & 3) * 2;
#pragma unroll
    for (int mi = 0; mi < 4; mi++)
#pragma unroll
        for (int ni = 0; ni < 4; ni++) {
            size_t row = (size_t)(bm + wm + mi * 16 + er);
            size_t col = (size_t)(bn + wn + ni * 8 + ec);
            *(float2*)&C[row * N + col]       = make_float2(acc[mi][ni][0], acc[mi][ni][1]);
            *(float2*)&C[(row + 8) * N + col] = make_float2(acc[mi][ni][2], acc[mi][ni][3]);
        }
}

// fused Q/K/V projection: bx 0-15 -> Q, 16-19 -> K, 20-23 -> V
__global__ __launch_bounds__(256, 2) void gemm_qkv_kernel(
    const __half* __restrict__ Ahi, const __half* __restrict__ Alo,
    const __half* __restrict__ Wq, const __half* __restrict__ Wk,
    const __half* __restrict__ Wv,
    float* __restrict__ Cq, float* __restrict__ Ck, float* __restrict__ Cv)
{
    extern __shared__ char smemg[];
    const uint32_t sbase = smem_u32(smemg);
    const int bx = blockIdx.x, bm = blockIdx.y * 128;
    const __half* Bh; float* C; int N, bn;
    if (bx < 16)      { Bh = Wq; C = Cq; N = NH_ * HD_;  bn = bx * 128; }
    else if (bx < 20) { Bh = Wk; C = Ck; N = NKV_ * HD_; bn = (bx - 16) * 128; }
    else              { Bh = Wv; C = Cv; N = NKV_ * HD_; bn = (bx - 20) * 128; }
    gemm_body(Ahi, Alo, Bh, C, N, H_, bm, bn, sbase);
}

// plain GEMM (out-proj)
__global__ __launch_bounds__(256, 2) void gemm_fp16_kernel(
    const __half* __restrict__ Ahi, const __half* __restrict__ Alo,
    const __half* __restrict__ Bh, float* __restrict__ C, int N, int K)
{
    extern __shared__ char smemg[];
    const uint32_t sbase = smem_u32(smemg);
    gemm_body(Ahi, Alo, Bh, C, N, K, blockIdx.y * 128, blockIdx.x * 128, sbase);
}

// ============================================================================
// Flash attention v2 on HMMA, 2-term fp16: S = (Qh+Ql)*Kh, O = (Ph+Pl)*Vh.
// Epilogue writes split fp16 hi/lo directly (feeds out-proj GEMM).
// ============================================================================
#define LDR   144
#define KVT   9216
#define KVSTG 18432
#define QOFF  36864
#define ATTN_SMEM 73728

#define KVPREF(buf, kv0v) do { \
    int r_ = tid >> 2; int qc_ = (tid & 3) * 32; \
    uint32_t so_ = sb + (buf) * KVSTG + r_ * LDR + qc_; \
    const char* kh_ = (const char*)(Kh + kvb + (size_t)((kv0v) + r_) * HD_) + qc_; \
    const char* vh_ = (const char*)(Vh + kvb + (size_t)((kv0v) + r_) * HD_) + qc_; \
    cp16(so_, kh_);         cp16(so_ + 16, kh_ + 16); \
    cp16(so_ + KVT, vh_);   cp16(so_ + KVT + 16, vh_ + 16); \
    CP_COMMIT(); \
} while (0)

__global__ __launch_bounds__(256, 2) void attn_hmma_kernel(
    const __half* __restrict__ Qh, const __half* __restrict__ Ql,
    const __half* __restrict__ Kh, const __half* __restrict__ Vh,
    __half* __restrict__ Ohh, __half* __restrict__ Ohl)
{
    extern __shared__ char sm[];
    const uint32_t sb = smem_u32(sm);
    const int qt = (S_ / 128 - 1) - blockIdx.x;
    const int h = blockIdx.y, b = blockIdx.z;
    const int hkv = h >> 2;
    const int tid = threadIdx.x, lane = tid & 31, w = tid >> 5;
    const int wq = w * 16, q0 = qt * 128;
    const int lmr = lane & 15, lmc = lane >> 4;
    const int g = lane >> 2, qd = lane & 3;
    const int vtr = lane & 7, vselk = (lane >> 3) & 1, vseln = lane >> 4;

    const __half* qhp = Qh + ((size_t)(b * NH_ + h) * S_ + q0) * HD_;
    const __half* qlp = Ql + ((size_t)(b * NH_ + h) * S_ + q0) * HD_;
    const size_t kvb = (size_t)(b * NKV_ + hkv) * S_ * HD_;

    // Q tiles into smem (once)
    {
        int r = tid >> 1;
        int cb = (tid & 1) * 64;
        uint32_t so = sb + QOFF + r * LDR + cb;
        const char* gh = (const char*)(qhp + (size_t)r * HD_) + cb;
        const char* gl = (const char*)(qlp + (size_t)r * HD_) + cb;
        cp16(so, gh);      cp16(so + 16, gh + 16);
        cp16(so + 32, gh + 32); cp16(so + 48, gh + 48);
        cp16(so + 18432, gl);      cp16(so + 18432 + 16, gl + 16);
        cp16(so + 18432 + 32, gl + 32); cp16(so + 18432 + 48, gl + 48);
        CP_COMMIT();
    }

    float m0 = -1e30f, m1 = -1e30f, l0 = 0.f, l1 = 0.f;
    float o[8][4];
#pragma unroll
    for (int nb = 0; nb < 8; nb++)
#pragma unroll
        for (int e = 0; e < 4; e++) o[nb][e] = 0.f;

    const int nch = 2 * (qt + 1);
    KVPREF(0, 0);

    for (int j = 0; j < nch; j++) {
        CP_WAIT0();
        __syncthreads();
        if (j + 1 < nch) KVPREF((j + 1) & 1, (j + 1) * 64);

        const uint32_t sKh = sb + (j & 1) * KVSTG;
        const uint32_t sVh = sKh + KVT;

        // ---- S = Q Kh^T (2 terms) ----
        float sc[8][4];
#pragma unroll
        for (int nb = 0; nb < 8; nb++)
#pragma unroll
            for (int e = 0; e < 4; e++) sc[nb][e] = 0.f;

#pragma unroll
        for (int kt = 0; kt < 4; kt++) {
            uint32_t qh_[4], ql_[4];
            uint32_t qro = QOFF + (wq + lmr) * LDR + (kt * 2 + lmc) * 16;
            ldmx4(qh_, sb + qro);
            ldmx4(ql_, sb + qro + 18432);
#pragma unroll
            for (int ng = 0; ng < 4; ng++) {
                uint32_t kh_[4];
                ldmx4(kh_, sKh + (ng * 16 + lmr) * LDR + (kt * 2 + lmc) * 16);
                mma16816(sc[2 * ng],     qh_, kh_[0], kh_[2]);
                mma16816(sc[2 * ng + 1], qh_, kh_[1], kh_[3]);
                mma16816(sc[2 * ng],     ql_, kh_[0], kh_[2]);
                mma16816(sc[2 * ng + 1], ql_, kh_[1], kh_[3]);
            }
        }

        // ---- causal mask ----
        const int kv0 = j * 64;
        if (kv0 + 63 > q0 + wq) {
            int row0 = q0 + wq + g;
#pragma unroll
            for (int nb = 0; nb < 8; nb++) {
                int col = kv0 + nb * 8 + qd * 2;
                if (col > row0)         sc[nb][0] = -1e30f;
                if (col + 1 > row0)     sc[nb][1] = -1e30f;
                if (col > row0 + 8)     sc[nb][2] = -1e30f;
                if (col + 1 > row0 + 8) sc[nb][3] = -1e30f;
            }
        }

        // ---- online softmax ----
        float mx0 = -1e30f, mx1 = -1e30f;
#pragma unroll
        for (int nb = 0; nb < 8; nb++) {
            mx0 = fmaxf(mx0, fmaxf(sc[nb][0], sc[nb][1]));
            mx1 = fmaxf(mx1, fmaxf(sc[nb][2], sc[nb][3]));
        }
        mx0 = fmaxf(mx0, __shfl_xor_sync(0xffffffffu, mx0, 1));
        mx0 = fmaxf(mx0, __shfl_xor_sync(0xffffffffu, mx0, 2));
        mx1 = fmaxf(mx1, __shfl_xor_sync(0xffffffffu, mx1, 1));
        mx1 = fmaxf(mx1, __shfl_xor_sync(0xffffffffu, mx1, 2));
        float nm0 = fmaxf(m0, mx0), nm1 = fmaxf(m1, mx1);
        float a0 = __expf(m0 - nm0), a1 = __expf(m1 - nm1);
        float rs0 = 0.f, rs1 = 0.f;
#pragma unroll
        for (int nb = 0; nb < 8; nb++) {
            sc[nb][0] = __expf(sc[nb][0] - nm0);
            sc[nb][1] = __expf(sc[nb][1] - nm0);
            sc[nb][2] = __expf(sc[nb][2] - nm1);
            sc[nb][3] = __expf(sc[nb][3] - nm1);
            rs0 += sc[nb][0] + sc[nb][1];
            rs1 += sc[nb][2] + sc[nb][3];
        }
        rs0 += __shfl_xor_sync(0xffffffffu, rs0, 1);
        rs0 += __shfl_xor_sync(0xffffffffu, rs0, 2);
        rs1 += __shfl_xor_sync(0xffffffffu, rs1, 1);
        rs1 += __shfl_xor_sync(0xffffffffu, rs1, 2);
        l0 = l0 * a0 + rs0; l1 = l1 * a1 + rs1;
        m0 = nm0; m1 = nm1;
#pragma unroll
        for (int nb = 0; nb < 8; nb++) {
            o[nb][0] *= a0; o[nb][1] *= a0;
            o[nb][2] *= a1; o[nb][3] *= a1;
        }

        // ---- O += P Vh (2 terms), P split from registers ----
#pragma unroll
        for (int kt = 0; kt < 4; kt++) {
            uint32_t pha[4], pla[4];
            splitpk(sc[2 * kt][0],     sc[2 * kt][1],     pha[0], pla[0]);
            splitpk(sc[2 * kt][2],     sc[2 * kt][3],     pha[1], pla[1]);
            splitpk(sc[2 * kt + 1][0], sc[2 * kt + 1][1], pha[2], pla[2]);
            splitpk(sc[2 * kt + 1][2], sc[2 * kt + 1][3], pha[3], pla[3]);
            uint32_t vrow = (kt * 16 + vselk * 8 + vtr) * LDR;
#pragma unroll
            for (int nb2 = 0; nb2 < 4; nb2++) {
                uint32_t vh_[4];
                ldmx4t(vh_, sVh + vrow + (nb2 * 2 + vseln) * 16);
                mma16816(o[2 * nb2],     pha, vh_[0], vh_[1]);
                mma16816(o[2 * nb2],     pla, vh_[0], vh_[1]);
                mma16816(o[2 * nb2 + 1], pha, vh_[2], vh_[3]);
                mma16816(o[2 * nb2 + 1], pla, vh_[2], vh_[3]);
            }
        }
    }

    // ---- epilogue: normalize + split to fp16 hi/lo directly ----
    float i0 = 1.f / l0, i1 = 1.f / l1;
    size_t base0 = ((size_t)(b * S_ + q0 + wq + g) * NH_ + h) * HD_;
    size_t base1 = base0 + (size_t)8 * NH_ * HD_;
#pragma unroll
    for (int nb = 0; nb < 8; nb++) {
        int col = nb * 8 + qd * 2;
        uint32_t hi, lo;
        splitpk(o[nb][0] * i0, o[nb][1] * i0, hi, lo);
        *(uint32_t*)(Ohh + base0 + col) = hi;
        *(uint32_t*)(Ohl + base0 + col) = lo;
        splitpk(o[nb][2] * i1, o[nb][3] * i1, hi, lo);
        *(uint32_t*)(Ohh + base1 + col) = hi;
        *(uint32_t*)(Ohl + base1 + col) = lo;
    }
}

// ============================================================================
extern "C" void kernel_launch(void* const* d_in, const int* in_sizes, int n_in,
                              void* d_out, int out_size)
{
    const float* hs = (const float*)d_in[0];
    const float* Wq = (const float*)d_in[1];
    const float* Wk = (const float*)d_in[2];
    const float* Wv = (const float*)d_in[3];
    const float* Wo = (const float*)d_in[4];
    float* out = (float*)d_out;

    float *qp, *kp, *vp;
    __half *hsh, *hsl, *wqh, *wkh, *wvh, *woh, *ohh, *ohl, *qh, *ql, *kh, *vh;
    cudaGetSymbolAddress((void**)&qp, g_q);
    cudaGetSymbolAddress((void**)&kp, g_k);
    cudaGetSymbolAddress((void**)&vp, g_v);
    cudaGetSymbolAddress((void**)&hsh, g_hs_hi);
    cudaGetSymbolAddress((void**)&hsl, g_hs_lo);
    cudaGetSymbolAddress((void**)&wqh, g_wq_hi);
    cudaGetSymbolAddress((void**)&wkh, g_wk_hi);
    cudaGetSymbolAddress((void**)&wvh, g_wv_hi);
    cudaGetSymbolAddress((void**)&woh, g_wo_hi);
    cudaGetSymbolAddress((void**)&ohh, g_oh_hi);
    cudaGetSymbolAddress((void**)&ohl, g_oh_lo);
    cudaGetSymbolAddress((void**)&qh, g_qh);
    cudaGetSymbolAddress((void**)&ql, g_ql);
    cudaGetSymbolAddress((void**)&kh, g_kh2);
    cudaGetSymbolAddress((void**)&vh, g_vh2);

    const int nHS = B_ * S_ * H_;

    cudaFuncSetAttribute(gemm_qkv_kernel, cudaFuncAttributeMaxDynamicSharedMemorySize, GEMM_SMEM);
    cudaFuncSetAttribute(gemm_fp16_kernel, cudaFuncAttributeMaxDynamicSharedMemorySize, GEMM_SMEM);
    cudaFuncSetAttribute(attn_hmma_kernel, cudaFuncAttributeMaxDynamicSharedMemorySize, ATTN_SMEM);

    // table + split hidden states + round all weights
    sincos_init_kernel<<<(S_ * 32) / 256, 256>>>();
    split_kernel<<<nHS / 4 / 256, 256>>>(hs, hsh, hsl, nHS / 4);
    round4_kernel<<<(N4_WQ + N4_WK + N4_WV + N4_WO) / 256, 256>>>(
        Wq, Wk, Wv, Wo, wqh, wkh, wvh, woh);

    // fused QKV projection
    gemm_qkv_kernel<<<dim3(24, 32), 256, GEMM_SMEM>>>(hsh, hsl, wqh, wkh, wvh, qp, kp, vp);

    // fused RoPE/split/round prep (table-driven)
    prep_kernel<<<(PREP_NQ + PREP_NK + PREP_NV + 255) / 256, 256>>>(
        qp, kp, vp, qh, ql, kh, vh);

    // attention (writes split fp16 hi/lo directly)
    attn_hmma_kernel<<<dim3(S_ / 128, NH_, B_), 256, ATTN_SMEM>>>(qh, ql, kh, vh, ohh, ohl);

    // out-proj
    gemm_fp16_kernel<<<dim3(16, 32), 256, GEMM_SMEM>>>(ohh, ohl, woh, out, H_, H_);
}

// round 15
// speedup vs baseline: 1.1472x; 1.1472x over previous
#include <cuda_runtime.h>
#include <cuda_fp16.h>
#include <math.h>
#include <cstdint>

// Problem dims
#define B_   2
#define S_   2048
#define H_   2048
#define NH_  32
#define NKV_ 8
#define HD_  64

// fp32 scratch (pre-rope Q/K/V)
__device__ float g_q[(size_t)B_ * S_ * NH_ * HD_];
__device__ float g_k[(size_t)B_ * S_ * NKV_ * HD_];
__device__ float g_v[(size_t)B_ * S_ * NKV_ * HD_];

// RoPE tables
__device__ float g_cos[S_ * 32];
__device__ float g_sin[S_ * 32];

// fp16 scratch
__device__ __half g_hs_hi[(size_t)B_ * S_ * H_];
__device__ __half g_hs_lo[(size_t)B_ * S_ * H_];
__device__ __half g_wq_hi[(size_t)H_ * H_];
__device__ __half g_wk_hi[(size_t)NKV_ * HD_ * H_];
__device__ __half g_wv_hi[(size_t)NKV_ * HD_ * H_];
__device__ __half g_wo_hi[(size_t)H_ * H_];
__device__ __half g_oh_hi[(size_t)B_ * S_ * NH_ * HD_];
__device__ __half g_oh_lo[(size_t)B_ * S_ * NH_ * HD_];
// attention operands, head-major [B, heads, S, HD]
__device__ __half g_qh[(size_t)B_ * NH_ * S_ * HD_];
__device__ __half g_ql[(size_t)B_ * NH_ * S_ * HD_];
__device__ __half g_kh2[(size_t)B_ * NKV_ * S_ * HD_];
__device__ __half g_vh2[(size_t)B_ * NKV_ * S_ * HD_];

// ---- mma.sync / ldmatrix / cp.async helpers ----
__device__ __forceinline__ uint32_t smem_u32(const void* p) {
    uint32_t a;
    asm("{ .reg .u64 t; cvta.to.shared.u64 t, %1; cvt.u32.u64 %0, t; }" : "=r"(a) : "l"(p));
    return a;
}
__device__ __forceinline__ void ldmx4(uint32_t* r, uint32_t addr) {
    asm volatile("ldmatrix.sync.aligned.m8n8.x4.shared.b16 {%0,%1,%2,%3}, [%4];"
                 : "=r"(r[0]), "=r"(r[1]), "=r"(r[2]), "=r"(r[3]) : "r"(addr));
}
__device__ __forceinline__ void ldmx4t(uint32_t* r, uint32_t addr) {
    asm volatile("ldmatrix.sync.aligned.m8n8.x4.trans.shared.b16 {%0,%1,%2,%3}, [%4];"
                 : "=r"(r[0]), "=r"(r[1]), "=r"(r[2]), "=r"(r[3]) : "r"(addr));
}
__device__ __forceinline__ void mma16816(float* c, const uint32_t* a, uint32_t b0, uint32_t b1) {
    asm volatile("mma.sync.aligned.m16n8k16.row.col.f32.f16.f16.f32 "
                 "{%0,%1,%2,%3}, {%4,%5,%6,%7}, {%8,%9}, {%0,%1,%2,%3};"
                 : "+f"(c[0]), "+f"(c[1]), "+f"(c[2]), "+f"(c[3])
                 : "r"(a[0]), "r"(a[1]), "r"(a[2]), "r"(a[3]), "r"(b0), "r"(b1));
}
__device__ __forceinline__ void cp16(uint32_t s, const void* g) {
    asm volatile("cp.async.ca.shared.global [%0], [%1], 16;" :: "r"(s), "l"(g));
}
#define CP_COMMIT() asm volatile("cp.async.commit_group;" ::: "memory")
#define CP_WAIT0()  asm volatile("cp.async.wait_group 0;" ::: "memory")

__device__ __forceinline__ uint32_t pkhf(float x, float y) {
    __half2 t = __floats2half2_rn(x, y);
    return *(uint32_t*)&t;
}
__device__ __forceinline__ void splitpk(float x, float y, uint32_t& hi, uint32_t& lo) {
    float hx = __half2float(__float2half_rn(x));
    float hy = __half2float(__float2half_rn(y));
    hi = pkhf(hx, hy);
    lo = pkhf(x - hx, y - hy);
}

// ============================================================================
// sincos table init
// ============================================================================
__global__ void sincos_init_kernel()
{
    int idx = blockIdx.x * blockDim.x + threadIdx.x;
    if (idx >= S_ * 32) return;
    int d = idx & 31, s = idx >> 5;
    float inv = exp2f((float)d * -0.41524101186f);
    float fr = (float)s * inv;
    float c, sn;
    sincosf(fr, &sn, &c);
    g_cos[idx] = c;
    g_sin[idx] = sn;
}

// ============================================================================
// split: fp32 -> fp16 hi + lo
// ============================================================================
__global__ void split_kernel(const float* __restrict__ x,
                             __half* __restrict__ hi,
                             __half* __restrict__ lo, int n4)
{
    int i = blockIdx.x * blockDim.x + threadIdx.x;
    if (i >= n4) return;
    float4 v = *(const float4*)(x + (size_t)i * 4);
    float h0 = __half2float(__float2half_rn(v.x));
    float h1 = __half2float(__float2half_rn(v.y));
    float h2 = __half2float(__float2half_rn(v.z));
    float h3 = __half2float(__float2half_rn(v.w));
    *(uint32_t*)(hi + (size_t)i * 4)     = pkhf(h0, h1);
    *(uint32_t*)(hi + (size_t)i * 4 + 2) = pkhf(h2, h3);
    *(uint32_t*)(lo + (size_t)i * 4)     = pkhf(v.x - h0, v.y - h1);
    *(uint32_t*)(lo + (size_t)i * 4 + 2) = pkhf(v.z - h2, v.w - h3);
}

// round all four weight matrices in one launch
#define N4_WQ 1048576
#define N4_WK 262144
#define N4_WV 262144
#define N4_WO 1048576
__global__ void round4_kernel(const float* __restrict__ wq, const float* __restrict__ wk,
                              const float* __restrict__ wv, const float* __restrict__ wo,
                              __half* __restrict__ oq, __half* __restrict__ ok,
                              __half* __restrict__ ov, __half* __restrict__ oo)
{
    int i = blockIdx.x * blockDim.x + threadIdx.x;
    const float* src; __half* dst; int j;
    if (i < N4_WQ)                      { src = wq; dst = oq; j = i; }
    else if (i < N4_WQ + N4_WK)         { src = wk; dst = ok; j = i - N4_WQ; }
    else if (i < N4_WQ + N4_WK + N4_WV) { src = wv; dst = ov; j = i - N4_WQ - N4_WK; }
    else if (i < N4_WQ + N4_WK + N4_WV + N4_WO)
                                        { src = wo; dst = oo; j = i - N4_WQ - N4_WK - N4_WV; }
    else return;
    float4 v = *(const float4*)(src + (size_t)j * 4);
    *(uint32_t*)(dst + (size_t)j * 4)     = pkhf(v.x, v.y);
    *(uint32_t*)(dst + (size_t)j * 4 + 2) = pkhf(v.z, v.w);
}

// ============================================================================
// Fused prep: rope+split(Q) | rope+round(K, scale 1/8) | round(V) -> head-major
// ============================================================================
#define PREP_NQ (B_ * S_ * NH_ * 32)            // 4194304
#define PREP_NK (B_ * S_ * NKV_ * 32)           // 1048576
#define PREP_NV (B_ * S_ * NKV_ * HD_ / 4)      // 1048576
__global__ void prep_kernel(const float* __restrict__ q, const float* __restrict__ k,
                            const float* __restrict__ v,
                            __half* __restrict__ qh, __half* __restrict__ ql,
                            __half* __restrict__ kh, __half* __restrict__ vh)
{
    int idx = blockIdx.x * blockDim.x + threadIdx.x;
    if (idx < PREP_NQ) {
        int d = idx & 31;
        int r = idx >> 5;
        int h = r & 31; r >>= 5;
        int s = r & (S_ - 1);
        int b = r >> 11;
        float c = g_cos[(s << 5) + d], sn = g_sin[(s << 5) + d];
        size_t src = (((size_t)b * S_ + s) * NH_ + h) * HD_;
        float x0 = q[src + d], x1 = q[src + d + 32];
        float y0 = x0 * c - x1 * sn;
        float y1 = x1 * c + x0 * sn;
        size_t dst = (((size_t)b * NH_ + h) * S_ + s) * HD_;
        float h0 = __half2float(__float2half_rn(y0));
        float h1 = __half2float(__float2half_rn(y1));
        qh[dst + d]      = __float2half_rn(h0);
        qh[dst + d + 32] = __float2half_rn(h1);
        ql[dst + d]      = __float2half_rn(y0 - h0);
        ql[dst + d + 32] = __float2half_rn(y1 - h1);
        return;
    }
    int i2 = idx - PREP_NQ;
    if (i2 < PREP_NK) {
        int d = i2 & 31;
        int r = i2 >> 5;
        int h = r & 7; r >>= 3;
        int s = r & (S_ - 1);
        int b = r >> 11;
        float c = g_cos[(s << 5) + d], sn = g_sin[(s << 5) + d];
        size_t src = (((size_t)b * S_ + s) * NKV_ + h) * HD_;
        float x0 = k[src + d], x1 = k[src + d + 32];
        size_t dst = (((size_t)b * NKV_ + h) * S_ + s) * HD_;
        kh[dst + d]      = __float2half_rn((x0 * c - x1 * sn) * 0.125f);
        kh[dst + d + 32] = __float2half_rn((x1 * c + x0 * sn) * 0.125f);
        return;
    }
    int i3 = i2 - PREP_NK;
    if (i3 >= PREP_NV) return;
    int d4 = i3 & 15; int r = i3 >> 4;
    int h = r & 7; r >>= 3;
    int s = r & (S_ - 1);
    int b = r >> 11;
    float4 vv = *(const float4*)(v + ((((size_t)b * S_ + s) * NKV_ + h) * HD_) + d4 * 4);
    size_t dst = (((size_t)b * NKV_ + h) * S_ + s) * HD_ + d4 * 4;
    *(uint32_t*)(vh + dst)     = pkhf(vv.x, vv.y);
    *(uint32_t*)(vh + dst + 2) = pkhf(vv.z, vv.w);
}

// ============================================================================
// HMMA GEMM body (R13-proven config): 2-term fp16, BK=32, 128x128 tile,
// 8 warps (2x4, 64x32 warp tiles), cp.async double buffer, LDB=80 rows
// (conflict-free ldmatrix), 61.4 KB total smem -> 2 CTA/SM.
// ============================================================================
#define LDB   80
#define TILEB (128 * LDB)
#define STAGEB (3 * TILEB)       // Ah, Al, Bh
#define GEMM_SMEM (2 * STAGEB)   // 61440

#define PREFETCH(buf, kcv) do { \
    size_t goff = (size_t)(kcv) * 32 + lc2 * 8; \
    uint32_t sro = (buf) * STAGEB + lrow * LDB + lc2 * 16; \
    const __half* _ga = Ahi + (size_t)(bm + lrow) * K + goff; \
    const __half* _gl = Alo + (size_t)(bm + lrow) * K + goff; \
    const __half* _gb = Bh  + (size_t)(bn + lrow) * K + goff; \
    cp16(sbase + sro,             _ga); cp16(sbase + sro + 16,             _ga + 8); \
    cp16(sbase + sro + TILEB,     _gl); cp16(sbase + sro + TILEB + 16,     _gl + 8); \
    cp16(sbase + sro + 2 * TILEB, _gb); cp16(sbase + sro + 2 * TILEB + 16, _gb + 8); \
    CP_COMMIT(); \
} while (0)

__device__ __forceinline__ void gemm_body(
    const __half* __restrict__ Ahi, const __half* __restrict__ Alo,
    const __half* __restrict__ Bh, float* __restrict__ C,
    int N, int K, int bm, int bn, uint32_t sbase)
{
    const int tid = threadIdx.x;
    const int lane = tid & 31, w = tid >> 5;
    const int wm = (w >> 2) * 64, wn = (w & 3) * 32;
    const int lrow = tid >> 1, lc2 = (tid & 1) * 2;
    const int lmr = lane & 15, lmc = lane >> 4;

    float acc[4][4][4];
#pragma unroll
    for (int a = 0; a < 4; a++)
#pragma unroll
        for (int b = 0; b < 4; b++)
#pragma unroll
            for (int c = 0; c < 4; c++) acc[a][b][c] = 0.f;

    const int nch = K >> 5;
    PREFETCH(0, 0);

    for (int it = 0; it < nch; it++) {
        CP_WAIT0();
        __syncthreads();
        if (it + 1 < nch) PREFETCH((it + 1) & 1, it + 1);

        const uint32_t sAh = sbase + (it & 1) * STAGEB;
        const uint32_t sAl = sAh + TILEB;
        const uint32_t sBh = sAh + 2 * TILEB;
#pragma unroll
        for (int kk = 0; kk < 2; kk++) {
            uint32_t bh[2][4];
#pragma unroll
            for (int nh = 0; nh < 2; nh++)
                ldmx4(bh[nh], sBh + (wn + nh * 16 + lmr) * LDB + (kk * 2 + lmc) * 16);
#pragma unroll
            for (int mi = 0; mi < 4; mi++) {
                uint32_t ah[4], al[4];
                uint32_t ro = (wm + mi * 16 + lmr) * LDB + (kk * 2 + lmc) * 16;
                ldmx4(ah, sAh + ro);
                ldmx4(al, sAl + ro);
#pragma unroll
                for (int nh = 0; nh < 2; nh++) {
                    mma16816(acc[mi][nh * 2 + 0], ah, bh[nh][0], bh[nh][2]);
                    mma16816(acc[mi][nh * 2 + 1], ah, bh[nh][1], bh[nh][3]);
                    mma16816(acc[mi][nh * 2 + 0], al, bh[nh][0], bh[nh][2]);
                    mma16816(acc[mi][nh * 2 + 1], al, bh[nh][1], bh[nh][3]);
                }
            }
        }
        __syncthreads();
    }

    const int er = lane >> 2, ec = (lane & 3) * 2;
#pragma unroll
    for (int mi = 0; mi < 4; mi++)
#pragma unroll
        for (int ni = 0; ni < 4; ni++) {
            size_t row = (size_t)(bm + wm + mi * 16 + er);
            size_t col = (size_t)(bn + wn + ni * 8 + ec);
            *(float2*)&C[row * N + col]       = make_float2(acc[mi][ni][0], acc[mi][ni][1]);
            *(float2*)&C[(row + 8) * N + col] = make_float2(acc[mi][ni][2], acc[mi][ni][3]);
        }
}

// fused Q/K/V projection: bx 0-15 -> Q, 16-19 -> K, 20-23 -> V
__global__ __launch_bounds__(256, 2) void gemm_qkv_kernel(
    const __half* __restrict__ Ahi, const __half* __restrict__ Alo,
    const __half* __restrict__ Wq, const __half* __restrict__ Wk,
    const __half* __restrict__ Wv,
    float* __restrict__ Cq, float* __restrict__ Ck, float* __restrict__ Cv)
{
    extern __shared__ char smemg[];
    const uint32_t sbase = smem_u32(smemg);
    const int bx = blockIdx.x, bm = blockIdx.y * 128;
    const __half* Bh; float* C; int N, bn;
    if (bx < 16)      { Bh = Wq; C = Cq; N = NH_ * HD_;  bn = bx * 128; }
    else if (bx < 20) { Bh = Wk; C = Ck; N = NKV_ * HD_; bn = (bx - 16) * 128; }
    else              { Bh = Wv; C = Cv; N = NKV_ * HD_; bn = (bx - 20) * 128; }
    gemm_body(Ahi, Alo, Bh, C, N, H_, bm, bn, sbase);
}

// plain GEMM (out-proj)
__global__ __launch_bounds__(256, 2) void gemm_fp16_kernel(
    const __half* __restrict__ Ahi, const __half* __restrict__ Alo,
    const __half* __restrict__ Bh, float* __restrict__ C, int N, int K)
{
    extern __shared__ char smemg[];
    const uint32_t sbase = smem_u32(smemg);
    gemm_body(Ahi, Alo, Bh, C, N, K, blockIdx.y * 128, blockIdx.x * 128, sbase);
}

// ============================================================================
// Flash attention v2 on HMMA, 2-term fp16: S = (Qh+Ql)*Kh, O = (Ph+Pl)*Vh.
// Epilogue writes split fp16 hi/lo directly (feeds out-proj GEMM).
// ============================================================================
#define LDR   144
#define KVT   9216
#define KVSTG 18432
#define QOFF  36864
#define ATTN_SMEM 73728

#define KVPREF(buf, kv0v) do { \
    int r_ = tid >> 2; int qc_ = (tid & 3) * 32; \
    uint32_t so_ = sb + (buf) * KVSTG + r_ * LDR + qc_; \
    const char* kh_ = (const char*)(Kh + kvb + (size_t)((kv0v) + r_) * HD_) + qc_; \
    const char* vh_ = (const char*)(Vh + kvb + (size_t)((kv0v) + r_) * HD_) + qc_; \
    cp16(so_, kh_);         cp16(so_ + 16, kh_ + 16); \
    cp16(so_ + KVT, vh_);   cp16(so_ + KVT + 16, vh_ + 16); \
    CP_COMMIT(); \
} while (0)

__global__ __launch_bounds__(256, 2) void attn_hmma_kernel(
    const __half* __restrict__ Qh, const __half* __restrict__ Ql,
    const __half* __restrict__ Kh, const __half* __restrict__ Vh,
    __half* __restrict__ Ohh, __half* __restrict__ Ohl)
{
    extern __shared__ char sm[];
    const uint32_t sb = smem_u32(sm);
    const int qt = (S_ / 128 - 1) - blockIdx.x;
    const int h = blockIdx.y, b = blockIdx.z;
    const int hkv = h >> 2;
    const int tid = threadIdx.x, lane = tid & 31, w = tid >> 5;
    const int wq = w * 16, q0 = qt * 128;
    const int lmr = lane & 15, lmc = lane >> 4;
    const int g = lane >> 2, qd = lane & 3;
    const int vtr = lane & 7, vselk = (lane >> 3) & 1, vseln = lane >> 4;

    const __half* qhp = Qh + ((size_t)(b * NH_ + h) * S_ + q0) * HD_;
    const __half* qlp = Ql + ((size_t)(b * NH_ + h) * S_ + q0) * HD_;
    const size_t kvb = (size_t)(b * NKV_ + hkv) * S_ * HD_;

    // Q tiles into smem (once)
    {
        int r = tid >> 1;
        int cb = (tid & 1) * 64;
        uint32_t so = sb + QOFF + r * LDR + cb;
        const char* gh = (const char*)(qhp + (size_t)r * HD_) + cb;
        const char* gl = (const char*)(qlp + (size_t)r * HD_) + cb;
        cp16(so, gh);      cp16(so + 16, gh + 16);
        cp16(so + 32, gh + 32); cp16(so + 48, gh + 48);
        cp16(so + 18432, gl);      cp16(so + 18432 + 16, gl + 16);
        cp16(so + 18432 + 32, gl + 32); cp16(so + 18432 + 48, gl + 48);
        CP_COMMIT();
    }

    float m0 = -1e30f, m1 = -1e30f, l0 = 0.f, l1 = 0.f;
    float o[8][4];
#pragma unroll
    for (int nb = 0; nb < 8; nb++)
#pragma unroll
        for (int e = 0; e < 4; e++) o[nb][e] = 0.f;

    const int nch = 2 * (qt + 1);
    KVPREF(0, 0);

    for (int j = 0; j < nch; j++) {
        CP_WAIT0();
        __syncthreads();
        if (j + 1 < nch) KVPREF((j + 1) & 1, (j + 1) * 64);

        const uint32_t sKh = sb + (j & 1) * KVSTG;
        const uint32_t sVh = sKh + KVT;

        // ---- S = Q Kh^T (2 terms) ----
        float sc[8][4];
#pragma unroll
        for (int nb = 0; nb < 8; nb++)
#pragma unroll
            for (int e = 0; e < 4; e++) sc[nb][e] = 0.f;

#pragma unroll
        for (int kt = 0; kt < 4; kt++) {
            uint32_t qh_[4], ql_[4];
            uint32_t qro = QOFF + (wq + lmr) * LDR + (kt * 2 + lmc) * 16;
            ldmx4(qh_, sb + qro);
            ldmx4(ql_, sb + qro + 18432);
#pragma unroll
            for (int ng = 0; ng < 4; ng++) {
                uint32_t kh_[4];
                ldmx4(kh_, sKh + (ng * 16 + lmr) * LDR + (kt * 2 + lmc) * 16);
                mma16816(sc[2 * ng],     qh_, kh_[0], kh_[2]);
                mma16816(sc[2 * ng + 1], qh_, kh_[1], kh_[3]);
                mma16816(sc[2 * ng],     ql_, kh_[0], kh_[2]);
                mma16816(sc[2 * ng + 1], ql_, kh_[1], kh_[3]);
            }
        }

        // ---- causal mask ----
        const int kv0 = j * 64;
        if (kv0 + 63 > q0 + wq) {
            int row0 = q0 + wq + g;
#pragma unroll
            for (int nb = 0; nb < 8; nb++) {
                int col = kv0 + nb * 8 + qd * 2;
                if (col > row0)         sc[nb][0] = -1e30f;
                if (col + 1 > row0)     sc[nb][1] = -1e30f;
                if (col > row0 + 8)     sc[nb][2] = -1e30f;
                if (col + 1 > row0 + 8) sc[nb][3] = -1e30f;
            }
        }

        // ---- online softmax ----
        float mx0 = -1e30f, mx1 = -1e30f;
#pragma unroll
        for (int nb = 0; nb < 8; nb++) {
            mx0 = fmaxf(mx0, fmaxf(sc[nb][0], sc[nb][1]));
            mx1 = fmaxf(mx1, fmaxf(sc[nb][2], sc[nb][3]));
        }
        mx0 = fmaxf(mx0, __shfl_xor_sync(0xffffffffu, mx0, 1));
        mx0 = fmaxf(mx0, __shfl_xor_sync(0xffffffffu, mx0, 2));
        mx1 = fmaxf(mx1, __shfl_xor_sync(0xffffffffu, mx1, 1));
        mx1 = fmaxf(mx1, __shfl_xor_sync(0xffffffffu, mx1, 2));
        float nm0 = fmaxf(m0, mx0), nm1 = fmaxf(m1, mx1);
        float a0 = __expf(m0 - nm0), a1 = __expf(m1 - nm1);
        float rs0 = 0.f, rs1 = 0.f;
#pragma unroll
        for (int nb = 0; nb < 8; nb++) {
            sc[nb][0] = __expf(sc[nb][0] - nm0);
            sc[nb][1] = __expf(sc[nb][1] - nm0);
            sc[nb][2] = __expf(sc[nb][2] - nm1);
            sc[nb][3] = __expf(sc[nb][3] - nm1);
            rs0 += sc[nb][0] + sc[nb][1];
            rs1 += sc[nb][2] + sc[nb][3];
        }
        rs0 += __shfl_xor_sync(0xffffffffu, rs0, 1);
        rs0 += __shfl_xor_sync(0xffffffffu, rs0, 2);
        rs1 += __shfl_xor_sync(0xffffffffu, rs1, 1);
        rs1 += __shfl_xor_sync(0xffffffffu, rs1, 2);
        l0 = l0 * a0 + rs0; l1 = l1 * a1 + rs1;
        m0 = nm0; m1 = nm1;
#pragma unroll
        for (int nb = 0; nb < 8; nb++) {
            o[nb][0] *= a0; o[nb][1] *= a0;
            o[nb][2] *= a1; o[nb][3] *= a1;
        }

        // ---- O += P Vh (2 terms), P split from registers ----
#pragma unroll
        for (int kt = 0; kt < 4; kt++) {
            uint32_t pha[4], pla[4];
            splitpk(sc[2 * kt][0],     sc[2 * kt][1],     pha[0], pla[0]);
            splitpk(sc[2 * kt][2],     sc[2 * kt][3],     pha[1], pla[1]);
            splitpk(sc[2 * kt + 1][0], sc[2 * kt + 1][1], pha[2], pla[2]);
            splitpk(sc[2 * kt + 1][2], sc[2 * kt + 1][3], pha[3], pla[3]);
            uint32_t vrow = (kt * 16 + vselk * 8 + vtr) * LDR;
#pragma unroll
            for (int nb2 = 0; nb2 < 4; nb2++) {
                uint32_t vh_[4];
                ldmx4t(vh_, sVh + vrow + (nb2 * 2 + vseln) * 16);
                mma16816(o[2 * nb2],     pha, vh_[0], vh_[1]);
                mma16816(o[2 * nb2],     pla, vh_[0], vh_[1]);
                mma16816(o[2 * nb2 + 1], pha, vh_[2], vh_[3]);
                mma16816(o[2 * nb2 + 1], pla, vh_[2], vh_[3]);
            }
        }
    }

    // ---- epilogue: normalize + split to fp16 hi/lo directly ----
    float i0 = 1.f / l0, i1 = 1.f / l1;
    size_t base0 = ((size_t)(b * S_ + q0 + wq + g) * NH_ + h) * HD_;
    size_t base1 = base0 + (size_t)8 * NH_ * HD_;
#pragma unroll
    for (int nb = 0; nb < 8; nb++) {
        int col = nb * 8 + qd * 2;
        uint32_t hi, lo;
        splitpk(o[nb][0] * i0, o[nb][1] * i0, hi, lo);
        *(uint32_t*)(Ohh + base0 + col) = hi;
        *(uint32_t*)(Ohl + base0 + col) = lo;
        splitpk(o[nb][2] * i1, o[nb][3] * i1, hi, lo);
        *(uint32_t*)(Ohh + base1 + col) = hi;
        *(uint32_t*)(Ohl + base1 + col) = lo;
    }
}

// ============================================================================
extern "C" void kernel_launch(void* const* d_in, const int* in_sizes, int n_in,
                              void* d_out, int out_size)
{
    const float* hs = (const float*)d_in[0];
    const float* Wq = (const float*)d_in[1];
    const float* Wk = (const float*)d_in[2];
    const float* Wv = (const float*)d_in[3];
    const float* Wo = (const float*)d_in[4];
    float* out = (float*)d_out;

    float *qp, *kp, *vp;
    __half *hsh, *hsl, *wqh, *wkh, *wvh, *woh, *ohh, *ohl, *qh, *ql, *kh, *vh;
    cudaGetSymbolAddress((void**)&qp, g_q);
    cudaGetSymbolAddress((void**)&kp, g_k);
    cudaGetSymbolAddress((void**)&vp, g_v);
    cudaGetSymbolAddress((void**)&hsh, g_hs_hi);
    cudaGetSymbolAddress((void**)&hsl, g_hs_lo);
    cudaGetSymbolAddress((void**)&wqh, g_wq_hi);
    cudaGetSymbolAddress((void**)&wkh, g_wk_hi);
    cudaGetSymbolAddress((void**)&wvh, g_wv_hi);
    cudaGetSymbolAddress((void**)&woh, g_wo_hi);
    cudaGetSymbolAddress((void**)&ohh, g_oh_hi);
    cudaGetSymbolAddress((void**)&ohl, g_oh_lo);
    cudaGetSymbolAddress((void**)&qh, g_qh);
    cudaGetSymbolAddress((void**)&ql, g_ql);
    cudaGetSymbolAddress((void**)&kh, g_kh2);
    cudaGetSymbolAddress((void**)&vh, g_vh2);

    const int nHS = B_ * S_ * H_;

    cudaFuncSetAttribute(gemm_qkv_kernel, cudaFuncAttributeMaxDynamicSharedMemorySize, GEMM_SMEM);
    cudaFuncSetAttribute(gemm_fp16_kernel, cudaFuncAttributeMaxDynamicSharedMemorySize, GEMM_SMEM);
    cudaFuncSetAttribute(attn_hmma_kernel, cudaFuncAttributeMaxDynamicSharedMemorySize, ATTN_SMEM);

    // table + split hidden states + round all weights
    sincos_init_kernel<<<(S_ * 32) / 256, 256>>>();
    split_kernel<<<nHS / 4 / 256, 256>>>(hs, hsh, hsl, nHS / 4);
    round4_kernel<<<(N4_WQ + N4_WK + N4_WV + N4_WO) / 256, 256>>>(
        Wq, Wk, Wv, Wo, wqh, wkh, wvh, woh);

    // fused QKV projection
    gemm_qkv_kernel<<<dim3(24, 32), 256, GEMM_SMEM>>>(hsh, hsl, wqh, wkh, wvh, qp, kp, vp);

    // fused RoPE/split/round prep (table-driven)
    prep_kernel<<<(PREP_NQ + PREP_NK + PREP_NV + 255) / 256, 256>>>(
        qp, kp, vp, qh, ql, kh, vh);

    // attention (writes split fp16 hi/lo directly)
    attn_hmma_kernel<<<dim3(S_ / 128, NH_, B_), 256, ATTN_SMEM>>>(qh, ql, kh, vh, ohh, ohl);

    // out-proj
    gemm_fp16_kernel<<<dim3(16, 32), 256, GEMM_SMEM>>>(ohh, ohl, woh, out, H_, H_);
}